// round 7
// baseline (speedup 1.0000x reference)
#include <cuda_runtime.h>

#define N     512
#define B     32
#define NF4   (N / 4)
#define NT    128
#define NWP   4
#define ROOTW 0xFFFF

__device__ double g_batch_sums[B];

// thread owns cols [4*tid, 4*tid+4); one float4 per thread per row (coalesced)
#define LOADROW(dst, row)                                                    \
    do {                                                                     \
        float4 _t = C4[(size_t)(row) * NF4 + tid];                           \
        dst[0] = _t.x; dst[1] = _t.y; dst[2] = _t.z; dst[3] = _t.w;          \
    } while (0)

__global__ __launch_bounds__(NT, 1)
void lap_kernel(const float* __restrict__ D)
{
    const int b    = blockIdx.x;
    const int tid  = threadIdx.x;
    const int lane = tid & 31;
    const int wrp  = tid >> 5;
    const int jc0  = tid << 2;
    const float*  __restrict__ C  = D + (size_t)b * N * N;
    const float4* __restrict__ C4 = (const float4*)C;

    __shared__ float          u[N];
    __shared__ int            prow[N];
    __shared__ unsigned short way[N];
    __shared__ float          dpop[N];
    __shared__ short          aminS[N];
    __shared__ unsigned char  rowUsed[N];
    __shared__ short          flist[3 * N];
    __shared__ short          alist[N];
    __shared__ int            s_nfree, s_iold, s_na;
    __shared__ unsigned       red1[2][NWP], red2[2][NWP];
    __shared__ uint2          redq[2][NWP];           // (warp-min key, its column)
    __shared__ double         red_s[NWP];

    for (int k = tid; k < N; k += NT) { u[k] = 0.f; prow[k] = -1; rowUsed[k] = 0; }

    const float INF = __uint_as_float(0x7F800000u);

    // ================= column reduction: v[j] = min_i C[i][j] ==============
    float v[4]; short amin[4];
#pragma unroll
    for (int k = 0; k < 4; ++k) { v[k] = INF; amin[k] = 0; }

    float c[4], cS[4], cT[4];
    for (int r = 0; r < N; r += 2) {
        float4 t0 = C4[(size_t)r * NF4 + tid];
        float4 t1 = C4[(size_t)(r + 1) * NF4 + tid];
        float a0[4] = {t0.x, t0.y, t0.z, t0.w};
        float a1[4] = {t1.x, t1.y, t1.z, t1.w};
#pragma unroll
        for (int k = 0; k < 4; ++k)
            if (a0[k] < v[k]) { v[k] = a0[k]; amin[k] = (short)r; }
#pragma unroll
        for (int k = 0; k < 4; ++k)
            if (a1[k] < v[k]) { v[k] = a1[k]; amin[k] = (short)(r + 1); }
    }
#pragma unroll
    for (int k = 0; k < 4; ++k) aminS[jc0 + k] = amin[k];
    __syncthreads();

    // ================= greedy assignment + lists (tid 0) ===================
    if (tid == 0) {
        for (int j = 0; j < N; ++j) {
            int i = aminS[j];
            if (!rowUsed[i]) { rowUsed[i] = 1; prow[j] = i; }
        }
        int nf = 0, na = 0;
        for (int i = 0; i < N; ++i)
            if (!rowUsed[i]) flist[nf++] = (short)i;
        for (int j = 0; j < N; ++j)
            if (prow[j] >= 0) alist[na++] = (short)j;
        s_nfree = nf; s_na = na;
    }
    __syncthreads();

    int pp = 0;

    // ================= JV reduction transfer ================================
    {
        const int na = s_na;
        if (na > 0) LOADROW(c, prow[alist[0]]);
        for (int t = 0; t < na; ++t) {
            const int j1 = alist[t];
            float m = INF;
#pragma unroll
            for (int k = 0; k < 4; ++k) {
                float rc = c[k] - v[k];
                if (jc0 + k == j1) rc = INF;
                m = fminf(m, rc);
            }
            if (t + 1 < na) LOADROW(c, prow[alist[t + 1]]);

            unsigned mb = __reduce_min_sync(0xffffffffu, __float_as_uint(m));
            if (lane == 0) red1[pp][wrp] = mb;
            __syncthreads();
            const float mu = __uint_as_float(min(min(red1[pp][0], red1[pp][1]),
                                                 min(red1[pp][2], red1[pp][3])));
            if ((unsigned)(j1 - jc0) < 4u) v[j1 - jc0] -= mu;
            if (tid == 0) u[prow[j1]] = mu;
            pp ^= 1;
        }
        __syncthreads();
    }

    int head = 0, tail = s_nfree;
    const int lim = 2 * tail;
    int cnt = 0;

    // ================= augmenting row reduction (bounded JV ARR) ===========
    if (head < tail) LOADROW(c, flist[0]);
    while (head < tail && cnt < lim) {
        const int i = flist[head]; ++head; ++cnt;

        unsigned kk[4];
#pragma unroll
        for (int k = 0; k < 4; ++k) {
            float r0 = c[k] - v[k];
            kk[k] = ((__float_as_uint(r0) + 0x200u) & ~0x3FFu) | (unsigned)(jc0 + k);
        }
        unsigned m = min(min(kk[0], kk[1]), min(kk[2], kk[3]));
        m = __reduce_min_sync(0xffffffffu, m);
        if (lane == 0) red1[pp][wrp] = m;

        unsigned m2 = 0xFFFFFFFFu;
        __syncthreads();                                            // bar 1
        const unsigned g1 = min(min(red1[pp][0], red1[pp][1]),
                                min(red1[pp][2], red1[pp][3]));
        const int j1 = (int)(g1 & 0x3FFu);

#pragma unroll
        for (int k = 0; k < 4; ++k) m2 = min(m2, (kk[k] == g1) ? 0xFFFFFFFFu : kk[k]);
        m2 = __reduce_min_sync(0xffffffffu, m2);
        if (lane == 0) red2[pp][wrp] = m2;
        __syncthreads();                                            // bar 2
        const unsigned g2 = min(min(red2[pp][0], red2[pp][1]),
                                min(red2[pp][2], red2[pp][3]));
        const int j2 = (int)(g2 & 0x3FFu);
        const float u1 = __uint_as_float(g1 & ~0x3FFu);
        const float u2 = __uint_as_float(g2 & ~0x3FFu);

        int jsel = j1;
        if (u1 < u2) {
            if ((unsigned)(j1 - jc0) < 4u) v[j1 - jc0] -= (u2 - u1);
        } else if (prow[j1] >= 0) {
            jsel = j2;
        }
        if (tid == 0) {
            int iold = prow[jsel];
            prow[jsel] = i;
            u[i] = u2;
            if (iold >= 0) flist[tail] = (short)iold;
            s_iold = iold;
        }
        pp ^= 1;
        __syncthreads();                                            // bar 3
        if (s_iold >= 0) ++tail;
        if (head < tail && cnt < lim) LOADROW(c, flist[head]);
    }

    // ================= shortest augmenting paths ===========================
    // Key format: [22-bit rounded value | 10-bit (prow[j]+1)], 0 = free col.
    if (head < tail) LOADROW(c, flist[head]);

    int ipred1 = -1, ipred2 = -1;

    for (int idx = head; idx < tail; ++idx) {
        const int i = flist[idx];

        // cache prow for my 4 columns (static during this Dijkstra)
        int4 pr4 = *(const int4*)&prow[jc0];
        unsigned prow1[4] = { (unsigned)(pr4.x + 1), (unsigned)(pr4.y + 1),
                              (unsigned)(pr4.z + 1), (unsigned)(pr4.w + 1) };

        float    uinf[4];
        unsigned key[4];
#pragma unroll
        for (int k = 0; k < 4; ++k) { uinf[k] = 0.f; key[k] = 0xFFFFFFFFu; }

        float          base = -u[i];
        unsigned short j0s  = ROOTW;
        int   jfreeC;
        float dfinal;

        while (true) {
            // ---- relax my 4 columns ----
#pragma unroll
            for (int k = 0; k < 4; ++k) {
                float cur   = fmaxf((c[k] - v[k]) + base, uinf[k]);
                unsigned pc = ((__float_as_uint(cur) + 0x200u) & ~0x3FFu)
                              | prow1[k];
                if (pc < key[k]) { key[k] = pc; way[jc0 + k] = j0s; }
            }
            unsigned m = min(min(key[0], key[1]), min(key[2], key[3]));
            const unsigned wm = __reduce_min_sync(0xffffffffu, m);
            if (m == wm) {                      // warp winner writes (key, col)
                unsigned jown = (key[0] == wm) ? jc0
                              : (key[1] == wm) ? jc0 + 1
                              : (key[2] == wm) ? jc0 + 2 : jc0 + 3;
                redq[pp][wrp] = make_uint2(wm, jown);
            }
            __syncthreads();                                        // ONE bar
            const uint2 q0 = redq[pp][0], q1 = redq[pp][1];
            const uint2 q2 = redq[pp][2], q3 = redq[pp][3];
            unsigned g = q0.x, jw = q0.y;
            if (q1.x < g) { g = q1.x; jw = q1.y; }
            if (q2.x < g) { g = q2.x; jw = q2.y; }
            if (q3.x < g) { g = q3.x; jw = q3.y; }

            const unsigned i1e = g & 0x3FFu;
            const float    dl  = __uint_as_float(g & ~0x3FFu);
            if (i1e == 0u) { jfreeC = (int)jw; dfinal = dl; pp ^= 1; break; }
            const int   i1  = (int)i1e - 1;
            const float ui1 = u[i1];            // LDS early, overlaps below

            // ---- pick row: 2-deep speculation keyed by ROW, else demand ----
            if (i1 == ipred1) {
#pragma unroll
                for (int k = 0; k < 4; ++k) c[k] = cS[k];
            } else if (i1 == ipred2) {
#pragma unroll
                for (int k = 0; k < 4; ++k) c[k] = cT[k];
            } else {
                LOADROW(c, i1);
            }

            // ---- owner poisons its popped column + records dpop ----
#pragma unroll
            for (int k = 0; k < 4; ++k)
                if (key[k] == g) {
                    uinf[k] = INF;
                    key[k]  = 0x7F800000u | prow1[k];
                    dpop[jc0 + k] = dl;
                }

            // ---- speculation: 2 smallest losing warp-minima carry rows ----
            {
                unsigned cA = 0xFFFFFFFFu, cB = 0xFFFFFFFFu;
                unsigned x;
                x = q0.x; if (x != g) { if (x < cA) { cB = cA; cA = x; } else cB = min(cB, x); }
                x = q1.x; if (x != g) { if (x < cA) { cB = cA; cA = x; } else cB = min(cB, x); }
                x = q2.x; if (x != g) { if (x < cA) { cB = cA; cA = x; } else cB = min(cB, x); }
                x = q3.x; if (x != g) { if (x < cA) { cB = cA; cA = x; } else cB = min(cB, x); }
                const int ipA = (int)(cA & 0x3FFu) - 1;
                const int ipB = (int)(cB & 0x3FFu) - 1;
                if (ipA >= 0 && cA < 0x7F800000u) { LOADROW(cS, ipA); ipred1 = ipA; }
                else ipred1 = -1;
                if (ipB >= 0 && cB < 0x7F800000u && ipB != ipred1) { LOADROW(cT, ipB); ipred2 = ipB; }
                else ipred2 = -1;
            }

            base = dl - ui1;
            j0s  = (unsigned short)jw;
            pp  ^= 1;
        }

        __syncthreads();              // all past break; dpop is self-owned

        // prefetch next root row before serial tail
        if (idx + 1 < tail) LOADROW(c, flist[idx + 1]);

        // ---- one-shot dual updates (prow from cached regs) ----
#pragma unroll
        for (int k = 0; k < 4; ++k) {
            if (uinf[k] > 0.f) {                  // col was popped
                float adj = dfinal - dpop[jc0 + k];
                v[k] -= adj;
                u[(int)prow1[k] - 1] += adj;      // distinct rows: race-free
            }
        }
        if (tid == 0) u[i] += dfinal;
        __syncthreads();

        // ---- augment along alternating path (serial, tid 0) ----
        if (tid == 0) {
            int j = jfreeC;
            while (true) {
                int jpth = way[j];
                if (jpth == ROOTW) { prow[j] = i; break; }
                prow[j] = prow[jpth];
                j = jpth;
            }
        }
        __syncthreads();
    }

    // ---- matched-cost sum (double, deterministic order) ----
    double s = 0.0;
#pragma unroll
    for (int k = 0; k < 4; ++k) {
        int j = jc0 + k;
        s += (double)__ldg(&C[(size_t)prow[j] * N + j]);
    }
#pragma unroll
    for (int off = 16; off; off >>= 1)
        s += __shfl_down_sync(0xffffffffu, s, off);
    if (lane == 0) red_s[wrp] = s;
    __syncthreads();
    if (tid == 0)
        g_batch_sums[b] = ((red_s[0] + red_s[1]) + (red_s[2] + red_s[3]));
}

__global__ void finalize_kernel(float* __restrict__ out)
{
    const int lane = threadIdx.x;
    double s = (lane < B) ? g_batch_sums[lane] : 0.0;
#pragma unroll
    for (int off = 16; off; off >>= 1)
        s += __shfl_down_sync(0xffffffffu, s, off);
    if (lane == 0) out[0] = (float)(s / (double)(B * N));
}

extern "C" void kernel_launch(void* const* d_in, const int* in_sizes, int n_in,
                              void* d_out, int out_size)
{
    const float* D = (const float*)d_in[0];
    lap_kernel<<<B, NT>>>(D);
    finalize_kernel<<<1, 32>>>((float*)d_out);
}